// round 6
// baseline (speedup 1.0000x reference)
#include <cuda_runtime.h>
#include <cuda_bf16.h>
#include <cstdint>
#include <cstddef>

// Problem constants
#define BB   256
#define TT   1024
#define FF   64
#define HH   128
#define GG   512   // 4*H

using u64 = unsigned long long;

// ---------------------------------------------------------------------------
// Packed f32x2 helpers (Blackwell sm_100a+)
// ---------------------------------------------------------------------------
__device__ __forceinline__ u64 ffma2(u64 a, u64 b, u64 c) {
    u64 d;
    asm("fma.rn.f32x2 %0, %1, %2, %3;" : "=l"(d) : "l"(a), "l"(b), "l"(c));
    return d;
}
__device__ __forceinline__ u64 pk(float x, float y) {
    u64 d; asm("mov.b64 %0, {%1, %2};" : "=l"(d) : "f"(x), "f"(y)); return d;
}
__device__ __forceinline__ float2 upk(u64 v) {
    float2 r; asm("mov.b64 {%0, %1}, %2;" : "=f"(r.x), "=f"(r.y) : "l"(v)); return r;
}

// ---------------------------------------------------------------------------
// Scratch (device globals; allocation in kernel_launch is forbidden)
// ---------------------------------------------------------------------------
__device__ float g_xg[(size_t)BB * TT * GG];   // 512 MB gate preactivations
__device__ float g_hs[(size_t)BB * TT * HH];   // 128 MB hidden states

// ---------------------------------------------------------------------------
// K1:  xg = x @ W_ih^T + (b_ih + b_hh)
//   Tile: 32 bt-rows x 128 gates per block, 256 threads.
//   Mapping: lane = row (0..31), warp = 16-gate group (8 warps x 16 = 128).
//   Weight LDS.128 is warp-uniform (broadcast); x is LDS.32 (2-way conflict).
//   Gates packed in pairs -> fma.rn.f32x2.
// ---------------------------------------------------------------------------
__global__ __launch_bounds__(256) void k1_xgemm(
    const float* __restrict__ x,
    const float* __restrict__ Wih,
    const float* __restrict__ bih,
    const float* __restrict__ bhh)
{
    __shared__ __align__(16) float xs[32][66];    // padded: bank = (2r + k) % 32
    __shared__ __align__(16) float ws[64][128];   // [k][gate] transposed, 32 KB

    const int bt0 = blockIdx.x * 32;
    const int g0  = blockIdx.y * 128;
    const int t   = threadIdx.x;

    // load x tile (32 rows x 64 k), float4 gmem -> 2x float2 smem (8B aligned)
    for (int i = t; i < 512; i += 256) {
        int row = i >> 4;
        int kq  = i & 15;
        float4 v = ((const float4*)(x + (size_t)(bt0 + row) * FF))[kq];
        *(float2*)&xs[row][kq * 4 + 0] = make_float2(v.x, v.y);
        *(float2*)&xs[row][kq * 4 + 2] = make_float2(v.z, v.w);
    }
    // load W tile transposed (128 gates x 64 k)
    for (int i = t; i < 2048; i += 256) {
        int g  = i >> 4;
        int kq = i & 15;
        float4 v = ((const float4*)(Wih + (size_t)(g0 + g) * FF))[kq];
        int k = kq * 4;
        ws[k + 0][g] = v.x;
        ws[k + 1][g] = v.y;
        ws[k + 2][g] = v.z;
        ws[k + 3][g] = v.w;
    }
    __syncthreads();

    const int lane = t & 31;          // row within tile
    const int wid  = t >> 5;          // 0..7 -> gate group
    const int gloc = wid * 16;        // local gate base (within 128)

    // init accumulators with bias (8 packed pairs = 16 gates)
    u64 acc[8];
#pragma unroll
    for (int p = 0; p < 8; p++) {
        int g = g0 + gloc + 2 * p;
        acc[p] = pk(bih[g] + bhh[g], bih[g + 1] + bhh[g + 1]);
    }

#pragma unroll 8
    for (int k = 0; k < 64; k++) {
        float xv = xs[lane][k];
        u64 xx = pk(xv, xv);
#pragma unroll
        for (int q = 0; q < 4; q++) {
            ulonglong2 wv = *(const ulonglong2*)&ws[k][gloc + q * 4];
            acc[2 * q]     = ffma2(xx, wv.x, acc[2 * q]);
            acc[2 * q + 1] = ffma2(xx, wv.y, acc[2 * q + 1]);
        }
    }

    // store 16 gates (4 float4), 64B contiguous per lane
    float* outp = g_xg + (size_t)(bt0 + lane) * GG + g0 + gloc;
#pragma unroll
    for (int q = 0; q < 4; q++) {
        float2 lo = upk(acc[2 * q]);
        float2 hi = upk(acc[2 * q + 1]);
        *(float4*)(outp + q * 4) = make_float4(lo.x, lo.y, hi.x, hi.y);
    }
}

// ---------------------------------------------------------------------------
// K2: persistent LSTM recurrence (64 clusters x 2 CTAs, as before) with:
//   - phase A packed over k-pairs via fma.rn.f32x2 (w held as 32 reg pairs)
//   - h relaid as [row][k] so LDS.128 feeds two packed k-pairs (broadcast)
//   - fast MUFU-based sigmoid/tanh
// ---------------------------------------------------------------------------
__device__ __forceinline__ float fsigm(float v) {
    return __fdividef(1.0f, 1.0f + __expf(-v));
}
__device__ __forceinline__ float ftanh(float v) {
    // saturation-safe: x->+inf => 1, x->-inf => -1 (no inf/inf)
    return 1.0f - __fdividef(2.0f, 1.0f + __expf(2.0f * v));
}

__global__ __launch_bounds__(512, 1) __cluster_dims__(2, 1, 1)
void k2_lstm(const float* __restrict__ Whh)
{
    __shared__ __align__(16) float hbuf[4][68];            // [row][k] padded
    __shared__ __align__(16) float pbuf[2][2][4][64][4];   // [parity][src][gt][j][row]

    const int t    = threadIdx.x;          // == global gate index
    const int rank = blockIdx.x & 1;
    const int cid  = blockIdx.x >> 1;
    const int rowBase = cid * 4;
    const int kOff = rank * 64;

    // --- load my W_hh row-half into 32 packed register pairs ---
    u64 w2[32];
    {
        const ulonglong2* wp = (const ulonglong2*)(Whh + (size_t)t * HH + kOff);
#pragma unroll
        for (int q = 0; q < 16; q++) {
            ulonglong2 v = wp[q];
            w2[2 * q]     = v.x;   // (w[4q],   w[4q+1])
            w2[2 * q + 1] = v.y;   // (w[4q+2], w[4q+3])
        }
    }

    // gate decomposition for partial routing
    const int gt    = t >> 7;        // gate type 0..3 (i,f,g,o)
    const int jg    = t & 127;       // h column of this gate
    const int owner = jg >> 6;       // owning CTA of that h column
    const int jl    = jg & 63;       // column local to owner
    const bool remote = (owner != rank);

    float* localDst = &pbuf[0][rank][gt][jl][0];
    uint32_t remoteAddr = 0;
    if (remote) {
        uint32_t la = (uint32_t)__cvta_generic_to_shared(localDst);
        asm volatile("mapa.shared::cluster.u32 %0, %1, %2;"
                     : "=r"(remoteAddr) : "r"(la), "r"(owner));
    }
    const uint32_t PAR_STRIDE = 2u * 4u * 64u * 4u * 4u;   // 8192 bytes

    // pointwise identity (first 256 threads): thread = (j, row)
    const int pj = t >> 2;
    const int pr = t & 3;
    const int pb = rowBase + pr;

    if (t < 256) hbuf[pr][pj] = 0.0f;
    float c = 0.0f;
    __syncthreads();

    for (int step = 0; step < TT; step++) {
        const int par = step & 1;

        // prefetch xg for my 4 owned gates (hidden under phase A)
        float xg0 = 0.f, xg1 = 0.f, xg2 = 0.f, xg3 = 0.f;
        if (t < 256) {
            size_t base = ((size_t)pb * TT + step) * GG + (size_t)(rank * 64 + pj);
            xg0 = g_xg[base];
            xg1 = g_xg[base + 128];
            xg2 = g_xg[base + 256];
            xg3 = g_xg[base + 384];
        }

        // --- phase A: packed split-K dot products (4 rows per thread) ---
        u64 a0 = 0, a1 = 0, a2 = 0, a3 = 0;   // (even-k, odd-k) partials
#pragma unroll
        for (int kq = 0; kq < 16; kq++) {
            ulonglong2 h0 = *(const ulonglong2*)&hbuf[0][kq * 4];
            ulonglong2 h1 = *(const ulonglong2*)&hbuf[1][kq * 4];
            ulonglong2 h2 = *(const ulonglong2*)&hbuf[2][kq * 4];
            ulonglong2 h3 = *(const ulonglong2*)&hbuf[3][kq * 4];
            u64 wa = w2[2 * kq], wb = w2[2 * kq + 1];
            a0 = ffma2(wa, h0.x, a0);  a0 = ffma2(wb, h0.y, a0);
            a1 = ffma2(wa, h1.x, a1);  a1 = ffma2(wb, h1.y, a1);
            a2 = ffma2(wa, h2.x, a2);  a2 = ffma2(wb, h2.y, a2);
            a3 = ffma2(wa, h3.x, a3);  a3 = ffma2(wb, h3.y, a3);
        }
        float2 s0 = upk(a0), s1 = upk(a1), s2 = upk(a2), s3 = upk(a3);
        float ax = s0.x + s0.y;
        float ay = s1.x + s1.y;
        float az = s2.x + s2.y;
        float aw = s3.x + s3.y;

        // --- route partials to the owning CTA ---
        if (!remote) {
            *(float4*)((char*)localDst + par * PAR_STRIDE) =
                make_float4(ax, ay, az, aw);
        } else {
            uint32_t a = remoteAddr + par * PAR_STRIDE;
            asm volatile("st.shared::cluster.f32 [%0], %1;" :: "r"(a),      "f"(ax) : "memory");
            asm volatile("st.shared::cluster.f32 [%0], %1;" :: "r"(a + 4),  "f"(ay) : "memory");
            asm volatile("st.shared::cluster.f32 [%0], %1;" :: "r"(a + 8),  "f"(az) : "memory");
            asm volatile("st.shared::cluster.f32 [%0], %1;" :: "r"(a + 12), "f"(aw) : "memory");
        }

        asm volatile("barrier.cluster.arrive.aligned;" ::: "memory");
        asm volatile("barrier.cluster.wait.aligned;"   ::: "memory");

        // --- pointwise LSTM update for my owned (row, column) ---
        if (t < 256) {
            float gi = xg0 + pbuf[par][0][0][pj][pr] + pbuf[par][1][0][pj][pr];
            float gf = xg1 + pbuf[par][0][1][pj][pr] + pbuf[par][1][1][pj][pr];
            float gc = xg2 + pbuf[par][0][2][pj][pr] + pbuf[par][1][2][pj][pr];
            float go = xg3 + pbuf[par][0][3][pj][pr] + pbuf[par][1][3][pj][pr];

            float iv = fsigm(gi);
            float fv = fsigm(gf);
            float gv = ftanh(gc);
            float ov = fsigm(go);

            c = fv * c + iv * gv;
            float h = ov * ftanh(c);

            hbuf[pr][pj] = h;
            g_hs[((size_t)pb * TT + step) * HH + (size_t)(rank * 64 + pj)] = h;
        }
        __syncthreads();   // h visible to all 512 threads before next phase A
    }
}

// ---------------------------------------------------------------------------
// K3: out = hs @ W_out^T.  hs: [BT, 128], W_out: [64, 128].
// ---------------------------------------------------------------------------
__global__ __launch_bounds__(256) void k3_proj(
    const float* __restrict__ Wout,
    float* __restrict__ out)
{
    __shared__ __align__(16) float hs_s[32][128];   // 16 KB
    __shared__ __align__(16) float ws[128][64];     // 32 KB, [k][f] transposed

    const int bt0 = blockIdx.x * 32;
    const int t   = threadIdx.x;

    for (int i = t; i < 1024; i += 256) {
        int row = i >> 5;
        int q   = i & 31;
        ((float4*)hs_s[row])[q] =
            ((const float4*)(g_hs + (size_t)(bt0 + row) * HH))[q];
    }
    for (int i = t; i < 2048; i += 256) {
        int f  = i >> 5;
        int kq = i & 31;
        float4 v = ((const float4*)(Wout + (size_t)f * HH))[kq];
        int k = kq * 4;
        ws[k + 0][f] = v.x;
        ws[k + 1][f] = v.y;
        ws[k + 2][f] = v.z;
        ws[k + 3][f] = v.w;
    }
    __syncthreads();

    const int tf = t & 15;
    const int tr = t >> 4;

    float4 acc0 = make_float4(0.f, 0.f, 0.f, 0.f);
    float4 acc1 = make_float4(0.f, 0.f, 0.f, 0.f);

#pragma unroll
    for (int k = 0; k < 128; k++) {
        float4 w4 = *(float4*)&ws[k][tf * 4];
        float h0 = hs_s[tr][k];
        float h1 = hs_s[tr + 16][k];
        acc0.x += h0 * w4.x; acc0.y += h0 * w4.y;
        acc0.z += h0 * w4.z; acc0.w += h0 * w4.w;
        acc1.x += h1 * w4.x; acc1.y += h1 * w4.y;
        acc1.z += h1 * w4.z; acc1.w += h1 * w4.w;
    }

    *(float4*)(out + (size_t)(bt0 + tr) * FF + tf * 4)      = acc0;
    *(float4*)(out + (size_t)(bt0 + tr + 16) * FF + tf * 4) = acc1;
}

// ---------------------------------------------------------------------------
// launch
// ---------------------------------------------------------------------------
extern "C" void kernel_launch(void* const* d_in, const int* in_sizes, int n_in,
                              void* d_out, int out_size)
{
    const float* x    = (const float*)d_in[0];  // [256,1024,64]
    const float* Wih  = (const float*)d_in[1];  // [512,64]
    const float* Whh  = (const float*)d_in[2];  // [512,128]
    const float* bih  = (const float*)d_in[3];  // [512]
    const float* bhh  = (const float*)d_in[4];  // [512]
    const float* Wout = (const float*)d_in[5];  // [64,128]
    float* out = (float*)d_out;                 // [256,1024,64]

    (void)in_sizes; (void)n_in; (void)out_size;

    k1_xgemm<<<dim3((BB * TT) / 32, 4), 256>>>(x, Wih, bih, bhh);
    k2_lstm<<<128, 512>>>(Whh);
    k3_proj<<<(BB * TT) / 32, 256>>>(Wout, out);
}